// round 1
// baseline (speedup 1.0000x reference)
#include <cuda_runtime.h>
#include <cuda_bf16.h>
#include <cstdint>

// Problem dims
#define BN 16
#define CH 64
#define HH 256
#define WW 256
#define HW (HH*WW)           // 65536
#define M_PER_CH (BN*HW)     // 1048576

// Scratch: conv output (bias omitted — it cancels in BN), stats
__device__ float g_conv[(size_t)BN*CH*HH*WW];   // 256 MB
__device__ float g_psum[CH*32];
__device__ float g_psq[CH*32];
__device__ float g_scale[CH];
__device__ float g_shift[CH];

// ---------------------------------------------------------------------------
// Kernel 1: direct dilated conv (k=3, dil=2, pad=2), no bias.
// Block tile: CO_T=16, H_T=16, W_T=32 (8192 outputs). 256 threads,
// each thread: 8 co x 4 w x 1 h  (32 accumulators).
// ---------------------------------------------------------------------------
__global__ __launch_bounds__(256) void conv_kernel(const float* __restrict__ x,
                                                   const float* __restrict__ wgt)
{
    __shared__ float sw[16*64*9];   // 36 KB: all weights for this co-group
    __shared__ float sx[20*37];     // padded x tile, conflict-free stride 37

    const int t  = threadIdx.x;
    const int wt = blockIdx.x;            // 0..7
    const int ht = blockIdx.y;            // 0..15
    const int nz = blockIdx.z;            // 0..63
    const int n   = nz >> 2;
    const int cog = nz & 3;
    const int w0 = wt * 32;
    const int h0 = ht * 16;

    const int wq = t & 7;          // w quad (4 px each)
    const int hq = (t >> 3) & 15;  // row within tile
    const int cq = t >> 7;         // co half (0/1)

    // Stage all 16co x 64ci x 9 weights once
    for (int idx = t; idx < 16*64*9; idx += 256)
        sw[idx] = wgt[cog*16*64*9 + idx];

    float acc[8][4];
    #pragma unroll
    for (int u = 0; u < 8; u++)
        #pragma unroll
        for (int j = 0; j < 4; j++) acc[u][j] = 0.f;

    const float* xn = x + (size_t)n * CH * HW;

    for (int ci = 0; ci < CH; ci++) {
        __syncthreads();   // protect sx from previous iteration's readers
        const float* xp = xn + ci * HW;
        // load 20x36 input tile (rows h0-2..h0+17, cols w0-2..w0+33)
        for (int idx = t; idx < 20*36; idx += 256) {
            int r = idx / 36, c = idx % 36;
            int gh = h0 + r - 2, gw = w0 + c - 2;
            float v = 0.f;
            if ((unsigned)gh < 256u && (unsigned)gw < 256u)
                v = xp[gh*WW + gw];
            sx[r*37 + c] = v;
        }
        __syncthreads();   // also covers the one-time weight staging

        // gather the 3x8 input window this thread needs
        float xv[3][8];
        #pragma unroll
        for (int rr = 0; rr < 3; rr++)
            #pragma unroll
            for (int cc = 0; cc < 8; cc++)
                xv[rr][cc] = sx[(hq + rr*2)*37 + wq*4 + cc];

        #pragma unroll
        for (int u = 0; u < 8; u++) {
            const float* wp = &sw[((cq*8 + u)*64 + ci)*9];
            float wr[9];
            #pragma unroll
            for (int k = 0; k < 9; k++) wr[k] = wp[k];
            #pragma unroll
            for (int kh = 0; kh < 3; kh++)
                #pragma unroll
                for (int kw = 0; kw < 3; kw++)
                    #pragma unroll
                    for (int j = 0; j < 4; j++)
                        acc[u][j] = fmaf(xv[kh][j + 2*kw], wr[kh*3 + kw], acc[u][j]);
        }
    }

    const int h = h0 + hq;
    const int w = w0 + wq*4;
    #pragma unroll
    for (int u = 0; u < 8; u++) {
        int co = cog*16 + cq*8 + u;
        size_t off = (((size_t)(n*CH + co)) << 16) + h*WW + w;
        *(float4*)&g_conv[off] = make_float4(acc[u][0], acc[u][1], acc[u][2], acc[u][3]);
    }
}

// ---------------------------------------------------------------------------
// Kernel 2a: per-channel partial sum / sumsq (deterministic tree reduction)
// grid (32, 64): block b handles half of one n-plane of channel c.
// ---------------------------------------------------------------------------
__global__ __launch_bounds__(256) void stats_kernel()
{
    const int c = blockIdx.y;
    const int b = blockIdx.x;             // 0..31
    const int t = threadIdx.x;
    const int n = b >> 1;
    const int half = b & 1;

    const float4* p = (const float4*)(g_conv + (((size_t)(n*CH + c)) << 16) + (half << 15));
    float s = 0.f, q = 0.f;
    #pragma unroll 8
    for (int i = 0; i < 32; i++) {
        float4 v = p[t + i*256];
        s += v.x + v.y + v.z + v.w;
        q += v.x*v.x + v.y*v.y + v.z*v.z + v.w*v.w;
    }
    __shared__ float ss[256], sq[256];
    ss[t] = s; sq[t] = q;
    __syncthreads();
    for (int st = 128; st > 0; st >>= 1) {
        if (t < st) { ss[t] += ss[t+st]; sq[t] += sq[t+st]; }
        __syncthreads();
    }
    if (t == 0) { g_psum[c*32 + b] = ss[0]; g_psq[c*32 + b] = sq[0]; }
}

// ---------------------------------------------------------------------------
// Kernel 2b: finalize mean/var -> scale/shift  (bias cancels; not needed)
// ---------------------------------------------------------------------------
__global__ void finalize_stats(const float* __restrict__ gamma,
                               const float* __restrict__ beta)
{
    int c = threadIdx.x;   // 64 threads
    float s = 0.f, q = 0.f;
    for (int b = 0; b < 32; b++) { s += g_psum[c*32 + b]; q += g_psq[c*32 + b]; }
    const float invM = 1.f / (float)M_PER_CH;
    float m   = s * invM;
    float var = q * invM - m*m;
    float inv = rsqrtf(var + 1e-5f);
    float sc  = gamma[c] * inv;
    g_scale[c] = sc;
    g_shift[c] = beta[c] - sc * m;
}

// ---------------------------------------------------------------------------
// Kernel 3: normalize + ReLU + 4x4 block bitonic sort; write [a | y]
// One thread per 4x4 spatial block.
// ---------------------------------------------------------------------------
__global__ __launch_bounds__(256) void bn_sort_kernel(float* __restrict__ out)
{
    int tid = blockIdx.x * 256 + threadIdx.x;      // 0 .. 4194303
    int bw = tid & 63;
    int bh = (tid >> 6) & 63;
    int c  = (tid >> 12) & 63;
    int n  = tid >> 18;

    float sc = g_scale[c];
    float sh = g_shift[c];

    size_t ibase = ((((size_t)(n*CH + c)) << 8) + bh*4) * WW + bw*4;
    float v[16];
    #pragma unroll
    for (int r = 0; r < 4; r++) {
        float4 q = *(const float4*)&g_conv[ibase + (size_t)r*WW];
        v[r*4+0] = fmaxf(fmaf(q.x, sc, sh), 0.f);
        v[r*4+1] = fmaxf(fmaf(q.y, sc, sh), 0.f);
        v[r*4+2] = fmaxf(fmaf(q.z, sc, sh), 0.f);
        v[r*4+3] = fmaxf(fmaf(q.w, sc, sh), 0.f);
    }

    size_t obase = ((((size_t)(n*128 + c)) << 8) + bh*4) * WW + bw*4;
    #pragma unroll
    for (int r = 0; r < 4; r++)
        *(float4*)&out[obase + (size_t)r*WW] =
            make_float4(v[r*4+0], v[r*4+1], v[r*4+2], v[r*4+3]);

    // bitonic sort 16 (ascending), fully unrolled -> min/max network
    #pragma unroll
    for (int k = 2; k <= 16; k <<= 1) {
        #pragma unroll
        for (int j = k >> 1; j > 0; j >>= 1) {
            #pragma unroll
            for (int i = 0; i < 16; i++) {
                int ix = i ^ j;
                if (ix > i) {
                    float a = v[i], b = v[ix];
                    float lo = fminf(a, b), hi = fmaxf(a, b);
                    bool up = ((i & k) == 0);
                    v[i]  = up ? lo : hi;
                    v[ix] = up ? hi : lo;
                }
            }
        }
    }

    size_t ybase = obase + ((size_t)64 << 16);   // channel c+64
    #pragma unroll
    for (int r = 0; r < 4; r++)
        *(float4*)&out[ybase + (size_t)r*WW] =
            make_float4(v[r*4+0], v[r*4+1], v[r*4+2], v[r*4+3]);
}

// ---------------------------------------------------------------------------
extern "C" void kernel_launch(void* const* d_in, const int* in_sizes, int n_in,
                              void* d_out, int out_size)
{
    const float* x     = (const float*)d_in[0];
    const float* wgt   = (const float*)d_in[1];
    // d_in[2] = conv_b : mathematically cancelled by training-mode BN
    const float* gamma = (const float*)d_in[3];
    const float* beta  = (const float*)d_in[4];
    float* out = (float*)d_out;

    conv_kernel<<<dim3(8, 16, 64), 256>>>(x, wgt);
    stats_kernel<<<dim3(32, 64), 256>>>();
    finalize_stats<<<1, 64>>>(gamma, beta);
    bn_sort_kernel<<<16384, 256>>>(out);
}